// round 4
// baseline (speedup 1.0000x reference)
#include <cuda_runtime.h>
#include <cstdint>

// Problem dims
#define BZc   8
#define NUMc  1024
#define NAc   64
#define FDc   128

typedef unsigned long long u64;
typedef unsigned int u32;

// ---------------- packed f32x2 helpers ----------------
__device__ __forceinline__ u64 pk2(float a, float b) {
    u64 r; asm("mov.b64 %0, {%1,%2};" : "=l"(r) : "f"(a), "f"(b)); return r;
}
__device__ __forceinline__ void upk2(u64 v, float& a, float& b) {
    asm("mov.b64 {%0,%1}, %2;" : "=f"(a), "=f"(b) : "l"(v));
}
__device__ __forceinline__ u64 ffma2(u64 a, u64 b, u64 c) {
    u64 d; asm("fma.rn.f32x2 %0, %1, %2, %3;" : "=l"(d) : "l"(a), "l"(b), "l"(c)); return d;
}
// HW tanh approx (1 MUFU) — hidden activations only.
__device__ __forceinline__ float tanha(float x) {
    float y; asm("tanh.approx.f32 %0, %1;" : "=f"(y) : "f"(x)); return y;
}
// Fast *precise* tanh: ex2 + rcp with one Newton step (~4e-7 err). Head only.
__device__ __forceinline__ float tanhp(float x) {
    float t; asm("ex2.approx.f32 %0, %1;" : "=f"(t) : "f"(x * 2.8853900817779268f));
    float d = 1.0f + t;
    float r; asm("rcp.approx.f32 %0, %1;" : "=f"(r) : "f"(d));
    r = fmaf(fmaf(-d, r, 1.0f), r, r);        // Newton refine
    return fmaf(-2.0f, r, 1.0f);              // 1 - 2/(1+e^{2x})
}
__device__ __forceinline__ float to_tf32(float x) {
    float y; asm("cvt.rna.tf32.f32 %0, %1;" : "=f"(y) : "f"(x)); return y;
}
__device__ __forceinline__ void mma_tf32(float d[4],
    u32 a0, u32 a1, u32 a2, u32 a3, u32 b0, u32 b1)
{
    asm("mma.sync.aligned.m16n8k8.row.col.f32.tf32.tf32.f32 "
        "{%0,%1,%2,%3}, {%4,%5,%6,%7}, {%8,%9}, {%0,%1,%2,%3};"
        : "+f"(d[0]), "+f"(d[1]), "+f"(d[2]), "+f"(d[3])
        : "r"(a0), "r"(a1), "r"(a2), "r"(a3), "r"(b0), "r"(b1));
}

// ---------------- folded weight storage (device globals) ----------------
__device__ float g_Wt[64 * FDc];  // tf32-rounded folded layer-1 weights [o][c]
__device__ float g_c1[64];
__device__ u64   g_Mf[64][16];
__device__ u64   g_Ms[16][16];
__device__ float g_ca[32];
__device__ float g_B1[8][4];
__device__ float g_d1[8];
__device__ float g_B2[16][8];
__device__ float g_d2[16];
__device__ float g_Wa2[32];
__device__ float g_ba2s;

// ---------------- weight folding kernel ----------------
__global__ void disarm_prep(
    const float* __restrict__ Wf1, const float* __restrict__ bf1,
    const float* __restrict__ gf1, const float* __restrict__ btf1,
    const float* __restrict__ Wf2, const float* __restrict__ bf2,
    const float* __restrict__ Ws1, const float* __restrict__ bs1,
    const float* __restrict__ gs1, const float* __restrict__ bts1,
    const float* __restrict__ Ws2, const float* __restrict__ bs2,
    const float* __restrict__ gs2, const float* __restrict__ bts2,
    const float* __restrict__ Ws3, const float* __restrict__ bs3,
    const float* __restrict__ Wa1, const float* __restrict__ ba1,
    const float* __restrict__ ga1, const float* __restrict__ bta1,
    const float* __restrict__ Wa2, const float* __restrict__ ba2)
{
    const float inv = rsqrtf(1.0f + 1e-5f);
    const int t = threadIdx.x;
    const int nt = blockDim.x;

    // Folded layer-1, tf32-rounded, row-major [o][c]
    for (int i = t; i < 64 * FDc; i += nt) {
        int o = i >> 7, c = i & 127;
        g_Wt[i] = to_tf32(gf1[o] * inv * Wf1[o * FDc + c]);
    }
    for (int i = t; i < 64; i += nt) g_c1[i] = gf1[i]*inv*bf1[i] + btf1[i];

    // Mf[h][q]: o = 2q, 2q+1 : ga1[o]*inv * sum_k Wa1[o][32+k]*Wf2[k][h]
    for (int i = t; i < 64 * 16; i += nt) {
        int h = i >> 4, q = i & 15;
        float v[2];
        #pragma unroll
        for (int s = 0; s < 2; ++s) {
            int o = 2*q + s;
            float acc = 0.0f;
            for (int k = 0; k < 32; ++k) acc += Wa1[o*64 + 32 + k] * Wf2[k*64 + h];
            v[s] = ga1[o] * inv * acc;
        }
        g_Mf[h][q] = pk2(v[0], v[1]);
    }
    for (int i = t; i < 16 * 16; i += nt) {
        int n = i >> 4, q = i & 15;
        float v[2];
        #pragma unroll
        for (int s = 0; s < 2; ++s) {
            int o = 2*q + s;
            float acc = 0.0f;
            for (int m = 0; m < 32; ++m) acc += Wa1[o*64 + m] * Ws3[m*16 + n];
            v[s] = ga1[o] * inv * acc;
        }
        g_Ms[n][q] = pk2(v[0], v[1]);
    }
    if (t < 32) {
        float acc = 0.0f;
        for (int k = 0; k < 32; ++k) acc += Wa1[t*64 + 32 + k] * bf2[k];
        for (int m = 0; m < 32; ++m) acc += Wa1[t*64 + m] * bs3[m];
        g_ca[t] = ga1[t]*inv*(acc + ba1[t]) + bta1[t];
    }
    if (t < 8) {
        for (int i = 0; i < 3; ++i) g_B1[t][i] = gs1[t]*inv*Ws1[t*3 + i];
        g_B1[t][3] = 0.0f;
        g_d1[t] = gs1[t]*inv*bs1[t] + bts1[t];
    }
    if (t < 16) {
        for (int i = 0; i < 8; ++i) g_B2[t][i] = gs2[t]*inv*Ws2[t*8 + i];
        g_d2[t] = gs2[t]*inv*bs2[t] + bts2[t];
    }
    if (t < 32) g_Wa2[t] = Wa2[t];
    if (t == 0) g_ba2s = ba2[0];
}

// ---------------- smem layout (bytes) ----------------
#define XSTRIDE   72                        // floats per X row (bank-clean for B frags)
#define SM_X      0                         // 2*128*72*4 = 73728 B (aliased by th)
#define THSTRIDE  68                        // floats per th row (16B-aligned rows)
#define SM_MF     73728                     // 64*16*8 = 8192
#define SM_MS     (SM_MF + 8192)            // 2048
#define SM_C1     (SM_MS + 2048)            // 256
#define SM_CA     (SM_C1 + 256)             // 128
#define SM_WA2    (SM_CA + 128)             // 128
#define SM_B1     (SM_WA2 + 128)            // 128
#define SM_D1     (SM_B1 + 128)             // 32
#define SM_B2     (SM_D1 + 32)              // 512
#define SM_D2     (SM_B2 + 512)             // 64
#define SM_BA2    (SM_D2 + 64)              // 4
#define SM_TOTAL  (SM_BA2 + 16)

// ---------------- main fused kernel ----------------
// 256 threads, 2 (b,p) groups per CTA.
// Stage 1: tf32 mma, 4 warps per group, 16 output-rows per warp.
// Stage 2: 2 warps (SMSP-rotated), 1 group each, 64 anchors as (lane, lane+32).
__global__ void __launch_bounds__(256, 2) disarm_mma(
    const float* __restrict__ loc, const float* __restrict__ feat,
    float* __restrict__ out)
{
    extern __shared__ char smem[];
    float* sX  = (float*)(smem + SM_X);
    float* sTH = (float*)(smem + SM_X);                 // alias, used after mma
    ulonglong2 (*sMf)[8] = (ulonglong2 (*)[8])(smem + SM_MF);
    ulonglong2 (*sMs)[8] = (ulonglong2 (*)[8])(smem + SM_MS);
    float* sc1   = (float*)(smem + SM_C1);
    float* sca   = (float*)(smem + SM_CA);
    float* sWa2v = (float*)(smem + SM_WA2);
    float (*sB1)[4] = (float (*)[4])(smem + SM_B1);
    float* sd1   = (float*)(smem + SM_D1);
    float (*sB2)[8] = (float (*)[8])(smem + SM_B2);
    float* sd2   = (float*)(smem + SM_D2);
    float* sba2  = (float*)(smem + SM_BA2);

    const int tid  = threadIdx.x;
    const int warp = tid >> 5;
    const int lane = tid & 31;
    const int g8   = lane >> 2;     // 0..7
    const int t4   = lane & 3;      // 0..3
    const int grp  = warp >> 2;     // stage-1 group within CTA
    const int wM   = warp & 3;      // 16-output tile index

    const size_t cs = (size_t)NUMc * NAc;

    // ---- A fragments: folded tf32 weights, 64 regs/thread ----
    u32 A[64];
    {
        const float* W0 = g_Wt + (16 * wM + g8) * FDc;     // row g8
        const float* W8 = W0 + 8 * FDc;                    // row g8+8
        #pragma unroll
        for (int k = 0; k < 16; ++k) {
            int c0 = 8 * k + t4;
            A[4*k+0] = __float_as_uint(W0[c0]);
            A[4*k+1] = __float_as_uint(W8[c0]);
            A[4*k+2] = __float_as_uint(W0[c0 + 4]);
            A[4*k+3] = __float_as_uint(W8[c0 + 4]);
        }
    }

    // ---- stage weights into smem ----
    {
        u64* d2 = (u64*)&sMf[0][0]; const u64* s2 = &g_Mf[0][0];
        for (int i = tid; i < 64*16; i += 256) d2[i] = s2[i];
        u64* d3 = (u64*)&sMs[0][0]; const u64* s3 = &g_Ms[0][0];
        d3[tid] = s3[tid];
        if (tid < 64) sc1[tid] = g_c1[tid];
        if (tid < 32) { sca[tid] = g_ca[tid]; sWa2v[tid] = g_Wa2[tid]; }
        if (tid < 32) sB1[tid>>2][tid&3] = g_B1[tid>>2][tid&3];
        if (tid < 8)  sd1[tid] = g_d1[tid];
        if (tid < 128) sB2[tid>>3][tid&7] = g_B2[tid>>3][tid&7];
        if (tid < 16) sd2[tid] = g_d2[tid];
        if (tid == 0) sba2[0] = g_ba2s;
    }

    // ---- stage X tiles (tf32-rounded): warps 0-3 -> group 0, 4-7 -> group 1 ----
    {
        const int sgrp   = tid >> 7;           // 0 or 1
        const int wg_tid = tid & 127;
        const int gp     = blockIdx.x * 2 + sgrp;
        const int b      = gp >> 10;
        const int p      = gp & 1023;
        const float* fbase = feat + (size_t)b * FDc * cs + (size_t)p * NAc;
        float* sXg = sX + sgrp * FDc * XSTRIDE;
        for (int i = wg_tid; i < FDc * 16; i += 128) {
            int c = i >> 4, v = i & 15;
            float4 x = __ldg((const float4*)(fbase + (size_t)c * cs) + v);
            x.x = to_tf32(x.x); x.y = to_tf32(x.y);
            x.z = to_tf32(x.z); x.w = to_tf32(x.w);
            *(float4*)(sXg + c * XSTRIDE + 4 * v) = x;
        }
    }
    __syncthreads();

    // ---- stage 1: mma mainloop (128 mma per warp) ----
    float D[8][4];
    #pragma unroll
    for (int n = 0; n < 8; ++n) { D[n][0]=0.f; D[n][1]=0.f; D[n][2]=0.f; D[n][3]=0.f; }
    {
        const float* sXg = sX + grp * FDc * XSTRIDE;
        #pragma unroll
        for (int k = 0; k < 16; ++k) {
            const float* r0 = sXg + (8*k + t4) * XSTRIDE + g8;
            const float* r4 = r0 + 4 * XSTRIDE;
            #pragma unroll
            for (int n = 0; n < 8; ++n) {
                u32 b0 = __float_as_uint(r0[8*n]);
                u32 b1 = __float_as_uint(r4[8*n]);
                mma_tf32(D[n], A[4*k], A[4*k+1], A[4*k+2], A[4*k+3], b0, b1);
            }
        }
    }
    __syncthreads();   // all sX reads complete before aliasing with th

    // ---- epilogue: bias + tanh -> th[anchor][h] ----
    {
        const float c1a = sc1[16*wM + g8];
        const float c1b = sc1[16*wM + g8 + 8];
        float* thg = sTH + grp * NAc * THSTRIDE;
        const int ro = 16*wM + g8;
        #pragma unroll
        for (int n = 0; n < 8; ++n) {
            const int a0 = 8*n + 2*t4;
            thg[(a0    )*THSTRIDE + ro    ] = tanha(D[n][0] + c1a);
            thg[(a0 + 1)*THSTRIDE + ro    ] = tanha(D[n][1] + c1a);
            thg[(a0    )*THSTRIDE + ro + 8] = tanha(D[n][2] + c1b);
            thg[(a0 + 1)*THSTRIDE + ro + 8] = tanha(D[n][3] + c1b);
        }
    }
    __syncthreads();

    // ---- stage 2: two warps, rotated across SMSPs by blockIdx ----
    const int q  = blockIdx.x & 3;
    const int wA = q;                     // handles group 0
    const int wB = 4 + ((q + 1) & 3);     // handles group 1
    int sgrp;
    if (warp == wA) sgrp = 0;
    else if (warp == wB) sgrp = 1;
    else return;

    const int gp = blockIdx.x * 2 + sgrp;
    const int b  = gp >> 10;
    const int p  = gp & 1023;
    const int a0 = lane;                  // anchors (lane, lane+32)
    const int a1 = lane + 32;
    const float* thg = sTH + sgrp * NAc * THSTRIDE;

    // a2 init
    u64 a2[2][16];
    #pragma unroll
    for (int qq = 0; qq < 16; ++qq) {
        u64 init = pk2(sca[2*qq], sca[2*qq+1]);
        a2[0][qq] = init; a2[1][qq] = init;
    }

    // spatial branch per anchor -> Ms fold
    {
        const float* lpb = loc + ((size_t)(b*NUMc + p)) * NAc * 3;
        #pragma unroll
        for (int s = 0; s < 2; ++s) {
            const float* lp = lpb + (size_t)(s ? a1 : a0) * 3;
            const float l0 = lp[0], l1 = lp[1], l2 = lp[2];
            float s1v[8];
            #pragma unroll
            for (int j = 0; j < 8; ++j)
                s1v[j] = tanha(sB1[j][0]*l0 + sB1[j][1]*l1 + sB1[j][2]*l2 + sd1[j]);
            #pragma unroll
            for (int n = 0; n < 16; ++n) {
                float a = sd2[n];
                #pragma unroll
                for (int i = 0; i < 8; ++i) a += sB2[n][i] * s1v[i];
                const float t2 = tanha(a);
                const u64 xx = pk2(t2, t2);
                #pragma unroll
                for (int q2 = 0; q2 < 8; ++q2) {
                    ulonglong2 w = sMs[n][q2];
                    a2[s][2*q2]   = ffma2(w.x, xx, a2[s][2*q2]);
                    a2[s][2*q2+1] = ffma2(w.y, xx, a2[s][2*q2+1]);
                }
            }
        }
    }

    // Mf fold: th already tanh'd; Mf rows shared across both anchors
    #pragma unroll
    for (int j = 0; j < 64; j += 4) {
        const float4 h0 = *(const float4*)(thg + a0 * THSTRIDE + j);
        const float4 h1 = *(const float4*)(thg + a1 * THSTRIDE + j);
        const float ha[4] = {h0.x, h0.y, h0.z, h0.w};
        const float hb[4] = {h1.x, h1.y, h1.z, h1.w};
        #pragma unroll
        for (int jj = 0; jj < 4; ++jj) {
            const u64 xa = pk2(ha[jj], ha[jj]);
            const u64 xb = pk2(hb[jj], hb[jj]);
            const ulonglong2* r = sMf[j + jj];
            #pragma unroll
            for (int q2 = 0; q2 < 8; ++q2) {
                ulonglong2 w = r[q2];
                a2[0][2*q2]   = ffma2(w.x, xa, a2[0][2*q2]);
                a2[0][2*q2+1] = ffma2(w.y, xa, a2[0][2*q2+1]);
                a2[1][2*q2]   = ffma2(w.x, xb, a2[1][2*q2]);
                a2[1][2*q2+1] = ffma2(w.y, xb, a2[1][2*q2+1]);
            }
        }
    }

    // scalar head (fast-precise tanh)
    float lg[2];
    #pragma unroll
    for (int s = 0; s < 2; ++s) {
        float outv = sba2[0];
        #pragma unroll
        for (int qq = 0; qq < 16; ++qq) {
            float a, bb; upk2(a2[s][qq], a, bb);
            outv += sWa2v[2*qq] * tanhp(a) + sWa2v[2*qq+1] * tanhp(bb);
        }
        lg[s] = tanhp(outv);
    }

    // softmax over 64 anchors (pure warp shuffles) + min-max norm
    const unsigned m32 = 0xffffffffu;
    float mx = fmaxf(lg[0], lg[1]);
    float mn = fminf(lg[0], lg[1]);
    #pragma unroll
    for (int off = 16; off > 0; off >>= 1) {
        mx = fmaxf(mx, __shfl_xor_sync(m32, mx, off));
        mn = fminf(mn, __shfl_xor_sync(m32, mn, off));
    }
    const float e0 = expf(lg[0] - mx);
    const float e1 = expf(lg[1] - mx);
    float ssum = e0 + e1;
    #pragma unroll
    for (int off = 16; off > 0; off >>= 1) ssum += __shfl_xor_sync(m32, ssum, off);
    const float invs = 1.0f / ssum;

    const float w0  = e0 * invs;
    const float w1  = e1 * invs;
    const float wmn = expf(mn - mx) * invs;
    const float wmx = invs;
    const float k   = (1.0f + 1e-6f) / (wmx - wmn + 1e-6f);

    float* ob = out + (size_t)gp * NAc;
    float* on = ob + (size_t)BZc * NUMc * NAc;
    ob[a0] = w0;
    ob[a1] = w1;
    on[a0] = k * (w0 - wmn);
    on[a1] = k * (w1 - wmn);
}

// ---------------- launch ----------------
extern "C" void kernel_launch(void* const* d_in, const int* in_sizes, int n_in,
                              void* d_out, int out_size)
{
    const float* loc  = (const float*)d_in[0];
    const float* feat = (const float*)d_in[1];

    disarm_prep<<<1, 256>>>(
        (const float*)d_in[2],  (const float*)d_in[3],  (const float*)d_in[4],  (const float*)d_in[5],
        (const float*)d_in[6],  (const float*)d_in[7],
        (const float*)d_in[8],  (const float*)d_in[9],  (const float*)d_in[10], (const float*)d_in[11],
        (const float*)d_in[12], (const float*)d_in[13], (const float*)d_in[14], (const float*)d_in[15],
        (const float*)d_in[16], (const float*)d_in[17],
        (const float*)d_in[18], (const float*)d_in[19], (const float*)d_in[20], (const float*)d_in[21],
        (const float*)d_in[22], (const float*)d_in[23]);

    static int smem_set = 0;
    if (!smem_set) {
        cudaFuncSetAttribute(disarm_mma,
                             cudaFuncAttributeMaxDynamicSharedMemorySize, SM_TOTAL);
        smem_set = 1;
    }
    disarm_mma<<<(BZc * NUMc) / 2, 256, SM_TOTAL>>>(loc, feat, (float*)d_out);
}